// round 2
// baseline (speedup 1.0000x reference)
#include <cuda_runtime.h>
#include <cuda_bf16.h>
#include <math_constants.h>

#define D        128
#define NODES_MX 40000
#define EDGES_MX 640000
#define MC   21      // message-cache rows per node (smem)
#define CAP  128     // score cache per node (smem)
#define CAPE 128     // eid cache per node (smem)
#define SCALE_INV_SQRT_D 0.08838834764831845f

// ---------------- scratch (device globals) ----------------
__device__ float g_summed[NODES_MX * D];
__device__ float g_qk[NODES_MX * D];
__device__ float g_wm[NODES_MX * D];
__device__ float g_qb[NODES_MX];
__device__ float g_sums[NODES_MX];
__device__ float g_scores[EDGES_MX];        // overflow fallback only
__device__ int   g_counts[NODES_MX];
__device__ int   g_offsets[NODES_MX + 1];
__device__ int   g_cursor[NODES_MX];
__device__ int   g_eids[EDGES_MX];
__device__ float g_Wqk[D * D];   // Wq @ Wk^T
__device__ float g_Wvo[D * D];   // Wv @ Wo
__device__ float g_bqk[D];       // bq @ Wk^T
__device__ float g_wqb[D];       // Wq @ bk
__device__ float g_bvo[D];       // bv @ Wo
__device__ float g_bqb[1];       // bq . bk

// ---------------- init ----------------
__global__ void k_init(int N) {
    int i = blockIdx.x * blockDim.x + threadIdx.x;
    if (i < N) g_counts[i] = 0;
}

// ---------------- precompute fused weights ----------------
__global__ void k_pre(const float* __restrict__ Wk, const float* __restrict__ bk,
                      const float* __restrict__ Wv, const float* __restrict__ bv,
                      const float* __restrict__ Wq, const float* __restrict__ bq,
                      const float* __restrict__ Wo) {
    int i = blockIdx.x;     // 0..127
    int j = threadIdx.x;    // 0..127
    float a = 0.f, c = 0.f;
#pragma unroll 8
    for (int t = 0; t < D; t++) {
        a = fmaf(Wq[i * D + t], Wk[j * D + t], a);   // (Wq Wk^T)[i][j]
        c = fmaf(Wv[i * D + t], Wo[t * D + j], c);   // (Wv Wo)[i][j]
    }
    g_Wqk[i * D + j] = a;
    g_Wvo[i * D + j] = c;
    if (i == 0) {
        float b1 = 0.f, b2 = 0.f, b3 = 0.f;
#pragma unroll 8
        for (int t = 0; t < D; t++) {
            b1 = fmaf(bq[t], Wk[j * D + t], b1);     // (bq Wk^T)[j]
            b2 = fmaf(Wq[j * D + t], bk[t], b2);     // (Wq bk)[j]
            b3 = fmaf(bv[t], Wo[t * D + j], b3);     // (bv Wo)[j]
        }
        g_bqk[j] = b1; g_wqb[j] = b2; g_bvo[j] = b3;
        if (j == 0) {
            float b = 0.f;
            for (int t = 0; t < D; t++) b = fmaf(bq[t], bk[t], b);
            g_bqb[0] = b;
        }
    }
}

// ---------------- CSR build ----------------
__global__ void k_hist(const int* __restrict__ recv, int E) {
    for (int e = blockIdx.x * blockDim.x + threadIdx.x; e < E; e += gridDim.x * blockDim.x)
        atomicAdd(&g_counts[recv[e]], 1);
}

// fast single-block scan: each thread owns a contiguous chunk
__global__ void k_scan(int N) {
    const int T = 1024;
    int tid = threadIdx.x;
    int per = (N + T - 1) / T;
    int base = tid * per;
    int lim = N - base; if (lim < 0) lim = 0; if (lim > per) lim = per;
    int s = 0;
    for (int i = 0; i < lim; i++) s += g_counts[base + i];
    // block exclusive scan of per-thread sums
    __shared__ int wsum[32];
    int lane = tid & 31, wid = tid >> 5;
    int v = s;
#pragma unroll
    for (int off = 1; off < 32; off <<= 1) {
        int t = __shfl_up_sync(0xffffffffu, v, off);
        if (lane >= off) v += t;
    }
    if (lane == 31) wsum[wid] = v;
    __syncthreads();
    if (wid == 0) {
        int x = wsum[lane];
#pragma unroll
        for (int off = 1; off < 32; off <<= 1) {
            int t = __shfl_up_sync(0xffffffffu, x, off);
            if (lane >= off) x += t;
        }
        wsum[lane] = x;
    }
    __syncthreads();
    int run = (v - s) + (wid > 0 ? wsum[wid - 1] : 0);
    for (int i = 0; i < lim; i++) {
        int idx = base + i;
        g_offsets[idx] = run;
        g_cursor[idx]  = run;
        run += g_counts[idx];
    }
    if (tid == 0) g_offsets[N] = wsum[31];
}

__global__ void k_scatter(const int* __restrict__ recv, int E) {
    for (int e = blockIdx.x * blockDim.x + threadIdx.x; e < E; e += gridDim.x * blockDim.x) {
        int pos = atomicAdd(&g_cursor[recv[e]], 1);
        g_eids[pos] = e;
    }
}

// ---------------- pass 1: summed[n] = sum of messages over node's edges ----------------
__global__ void k_sum_nodes(const float* __restrict__ messages, int N) {
    __shared__ int se[4][CAPE];
    int w = threadIdx.x >> 5;
    int lane = threadIdx.x & 31;
    int n = blockIdx.x * 4 + w;
    if (n >= N) return;
    int beg = g_offsets[n], end = g_offsets[n + 1];
    int deg = end - beg;
    for (int k = lane; k < deg && k < CAPE; k += 32) se[w][k] = g_eids[beg + k];
    __syncwarp();
    const float4* m4 = (const float4*)messages;
    float4 acc = make_float4(0.f, 0.f, 0.f, 0.f);
    for (int k0 = 0; k0 < deg; k0 += 4) {
        float4 mm[4];
#pragma unroll
        for (int j = 0; j < 4; j++) {
            int k = k0 + j;
            if (k < deg) {
                int e = (k < CAPE) ? se[w][k] : g_eids[beg + k];
                mm[j] = __ldg(m4 + (size_t)e * 32 + lane);
            }
        }
#pragma unroll
        for (int j = 0; j < 4; j++) {
            int k = k0 + j;
            if (k < deg) {
                acc.x += mm[j].x; acc.y += mm[j].y;
                acc.z += mm[j].z; acc.w += mm[j].w;
            }
        }
    }
    ((float4*)g_summed)[(size_t)n * 32 + lane] = acc;
}

// ---------------- node projection: qk = summed @ Wqk + bqk ; qb = summed.wqb + bqb ----
__global__ void k_qkproj(int N) {
    const int TN = 16;
    __shared__ __align__(16) float ss[TN][D];
    int n0 = blockIdx.x * TN;
    int j = threadIdx.x;   // 0..127
#pragma unroll
    for (int u = 0; u < TN; u++) {
        int n = n0 + u; if (n >= N) n = N - 1;
        ss[u][j] = g_summed[(size_t)n * D + j];
    }
    __syncthreads();
    float acc[TN];
    float b = g_bqk[j];
#pragma unroll
    for (int u = 0; u < TN; u++) acc[u] = b;
    for (int i4 = 0; i4 < D / 4; i4++) {
        float w0 = g_Wqk[(4 * i4 + 0) * D + j];
        float w1 = g_Wqk[(4 * i4 + 1) * D + j];
        float w2 = g_Wqk[(4 * i4 + 2) * D + j];
        float w3 = g_Wqk[(4 * i4 + 3) * D + j];
#pragma unroll
        for (int u = 0; u < TN; u++) {
            float4 sv = ((const float4*)ss[u])[i4];
            acc[u] = fmaf(sv.x, w0, acc[u]);
            acc[u] = fmaf(sv.y, w1, acc[u]);
            acc[u] = fmaf(sv.z, w2, acc[u]);
            acc[u] = fmaf(sv.w, w3, acc[u]);
        }
    }
#pragma unroll
    for (int u = 0; u < TN; u++)
        if (n0 + u < N) g_qk[(size_t)(n0 + u) * D + j] = acc[u];
    if (j < TN && n0 + j < N) {
        float a = g_bqb[0];
        for (int i = 0; i < D; i++) a = fmaf(ss[j][i], g_wqb[i], a);
        g_qb[n0 + j] = a;
    }
}

// ---------------- fused: scores + node-local softmax + weighted aggregation ----------
__global__ void k_fused(const float* __restrict__ messages, int N) {
    __shared__ __align__(16) float4 mc[4][MC][32];   // message cache
    __shared__ float sc[4][CAP];                     // scores -> exp
    __shared__ int   se[4][CAPE];                    // edge ids
    int w = threadIdx.x >> 5;
    int lane = threadIdx.x & 31;
    int n = blockIdx.x * 4 + w;
    if (n >= N) return;
    int beg = g_offsets[n], end = g_offsets[n + 1];
    int deg = end - beg;
    const float4* m4 = (const float4*)messages;

    for (int k = lane; k < deg && k < CAPE; k += 32) se[w][k] = g_eids[beg + k];
    __syncwarp();

    float4 q = __ldg((const float4*)g_qk + (size_t)n * 32 + lane);
    float qb = __ldg(&g_qb[n]);

    // ---- pass B: scores + running max (warp-uniform) ----
    float runmax = -CUDART_INF_F;
    for (int k0 = 0; k0 < deg; k0 += 4) {
        float4 mm[4];
#pragma unroll
        for (int j = 0; j < 4; j++) {
            int k = k0 + j;
            if (k < deg) {
                int e = (k < CAPE) ? se[w][k] : g_eids[beg + k];
                mm[j] = __ldg(m4 + (size_t)e * 32 + lane);
            }
        }
#pragma unroll
        for (int j = 0; j < 4; j++) {
            int k = k0 + j;
            if (k < deg) {
                float4 m = mm[j];
                if (k < MC) mc[w][k][lane] = m;
                float d = m.x * q.x + m.y * q.y + m.z * q.z + m.w * q.w;
#pragma unroll
                for (int off = 16; off > 0; off >>= 1)
                    d += __shfl_xor_sync(0xffffffffu, d, off);
                float s_ = (d + qb) * SCALE_INV_SQRT_D;
                if (lane == 0) {
                    if (k < CAP) sc[w][k] = s_;
                    else         g_scores[beg + k] = s_;
                }
                runmax = fmaxf(runmax, s_);
            }
        }
    }
    __syncwarp();
    if (deg > CAP) __threadfence_block();

    // ---- softmax: exp + sum (warp-local) ----
    float p = 0.f;
    for (int k = lane; k < deg; k += 32) {
        float sv = (k < CAP) ? sc[w][k] : g_scores[beg + k];
        float ev = __expf(sv - runmax);
        p += ev;
        if (k < CAP) sc[w][k] = ev;
        else         g_scores[beg + k] = ev;
    }
#pragma unroll
    for (int off = 16; off > 0; off >>= 1)
        p += __shfl_xor_sync(0xffffffffu, p, off);
    float inv = 1.f / (p + 1e-8f);
    if (lane == 0) g_sums[n] = p;
    __syncwarp();
    if (deg > CAP) __threadfence_block();

    // ---- pass C: weighted aggregation (mostly from smem cache) ----
    float4 acc = make_float4(0.f, 0.f, 0.f, 0.f);
    int kc = deg < MC ? deg : MC;
    for (int k = 0; k < kc; k++) {
        float wgt = sc[w][k] * inv;      // k < MC <= CAP
        float4 m = mc[w][k][lane];
        acc.x = fmaf(wgt, m.x, acc.x); acc.y = fmaf(wgt, m.y, acc.y);
        acc.z = fmaf(wgt, m.z, acc.z); acc.w = fmaf(wgt, m.w, acc.w);
    }
    for (int k0 = MC; k0 < deg; k0 += 4) {
        float4 mm[4];
#pragma unroll
        for (int j = 0; j < 4; j++) {
            int k = k0 + j;
            if (k < deg) {
                int e = (k < CAPE) ? se[w][k] : g_eids[beg + k];
                mm[j] = __ldg(m4 + (size_t)e * 32 + lane);
            }
        }
#pragma unroll
        for (int j = 0; j < 4; j++) {
            int k = k0 + j;
            if (k < deg) {
                float wgt = ((k < CAP) ? sc[w][k] : g_scores[beg + k]) * inv;
                acc.x = fmaf(wgt, mm[j].x, acc.x); acc.y = fmaf(wgt, mm[j].y, acc.y);
                acc.z = fmaf(wgt, mm[j].z, acc.z); acc.w = fmaf(wgt, mm[j].w, acc.w);
            }
        }
    }
    ((float4*)g_wm)[(size_t)n * 32 + lane] = acc;
}

// ---------------- output projection: out = wm @ Wvo + asum*bvo + bo ----------------
__global__ void k_out(const float* __restrict__ bo, float* __restrict__ out, int N) {
    const int TN = 16;
    __shared__ __align__(16) float ss[TN][D];
    __shared__ float sas[TN];
    int n0 = blockIdx.x * TN;
    int j = threadIdx.x;
#pragma unroll
    for (int u = 0; u < TN; u++) {
        int n = n0 + u; if (n >= N) n = N - 1;
        ss[u][j] = g_wm[(size_t)n * D + j];
    }
    if (j < TN) {
        int n = n0 + j; if (n >= N) n = N - 1;
        float s = g_sums[n];
        sas[j] = s / (s + 1e-8f);
    }
    __syncthreads();
    float bvoj = g_bvo[j];
    float boj  = __ldg(bo + j);
    float acc[TN];
#pragma unroll
    for (int u = 0; u < TN; u++) acc[u] = fmaf(sas[u], bvoj, boj);
    for (int i4 = 0; i4 < D / 4; i4++) {
        float w0 = g_Wvo[(4 * i4 + 0) * D + j];
        float w1 = g_Wvo[(4 * i4 + 1) * D + j];
        float w2 = g_Wvo[(4 * i4 + 2) * D + j];
        float w3 = g_Wvo[(4 * i4 + 3) * D + j];
#pragma unroll
        for (int u = 0; u < TN; u++) {
            float4 sv = ((const float4*)ss[u])[i4];
            acc[u] = fmaf(sv.x, w0, acc[u]);
            acc[u] = fmaf(sv.y, w1, acc[u]);
            acc[u] = fmaf(sv.z, w2, acc[u]);
            acc[u] = fmaf(sv.w, w3, acc[u]);
        }
    }
#pragma unroll
    for (int u = 0; u < TN; u++)
        if (n0 + u < N) out[(size_t)(n0 + u) * D + j] = acc[u];
}

// ---------------- launch ----------------
extern "C" void kernel_launch(void* const* d_in, const int* in_sizes, int n_in,
                              void* d_out, int out_size) {
    const float* messages = (const float*)d_in[0];
    const int*   recv     = (const int*)d_in[1];
    int wb = (n_in >= 11) ? 3 : 2;
    const float* Wk = (const float*)d_in[wb + 0];
    const float* bk = (const float*)d_in[wb + 1];
    const float* Wv = (const float*)d_in[wb + 2];
    const float* bv = (const float*)d_in[wb + 3];
    const float* Wq = (const float*)d_in[wb + 4];
    const float* bq = (const float*)d_in[wb + 5];
    const float* Wo = (const float*)d_in[wb + 6];
    const float* bo = (const float*)d_in[wb + 7];
    float* out = (float*)d_out;

    int E = in_sizes[0] / D;
    int N = out_size / D;

    k_init<<<(N + 255) / 256, 256>>>(N);
    k_pre<<<D, D>>>(Wk, bk, Wv, bv, Wq, bq, Wo);
    k_hist<<<(E + 255) / 256, 256>>>(recv, E);
    k_scan<<<1, 1024>>>(N);
    k_scatter<<<(E + 255) / 256, 256>>>(recv, E);
    k_sum_nodes<<<(N + 3) / 4, 128>>>(messages, N);
    k_qkproj<<<(N + 15) / 16, 128>>>(N);
    k_fused<<<(N + 3) / 4, 128>>>(messages, N);
    k_out<<<(N + 15) / 16, 128>>>(bo, out, N);
}

// round 3
// speedup vs baseline: 1.3715x; 1.3715x over previous
#include <cuda_runtime.h>
#include <cuda_bf16.h>
#include <math_constants.h>

#define D        128
#define NODES_MX 40000
#define EDGES_MX 640000
#define SCALE_INV 0.08838834764831845f   // 1/sqrt(128)

// ---------------- scratch (device globals) ----------------
__device__ float g_summed[NODES_MX * D];
__device__ float g_qk[NODES_MX * D];
__device__ float g_wm[NODES_MX * D];
__device__ float g_qb[NODES_MX];
__device__ float g_sums[NODES_MX];
__device__ float g_scores[EDGES_MX];   // raw scores, CSR order (only used for deg>32 tail)
__device__ float g_att[EDGES_MX];      // normalized attention weights, CSR order
__device__ int   g_counts[NODES_MX];
__device__ int   g_offsets[NODES_MX + 1];
__device__ int   g_cursor[NODES_MX];
__device__ int   g_eids[EDGES_MX];
__device__ int   g_bsum[512];
__device__ float g_Wqk[D * D];   // Wq @ Wk^T
__device__ float g_Wvo[D * D];   // Wv @ Wo
__device__ float g_bqk[D];       // bq @ Wk^T
__device__ float g_wqb[D];       // Wq @ bk
__device__ float g_bvo[D];       // bv @ Wo
__device__ float g_bqb[1];       // bq . bk

// ---------------- f32x2 helpers ----------------
__device__ __forceinline__ unsigned long long ffma2(unsigned long long a,
                                                    unsigned long long b,
                                                    unsigned long long c) {
    unsigned long long d;
    asm("fma.rn.f32x2 %0, %1, %2, %3;" : "=l"(d) : "l"(a), "l"(b), "l"(c));
    return d;
}
__device__ __forceinline__ unsigned long long pk2(float lo, float hi) {
    unsigned long long r;
    asm("mov.b64 %0, {%1, %2};" : "=l"(r) : "f"(lo), "f"(hi));
    return r;
}
__device__ __forceinline__ float2 upk2(unsigned long long v) {
    float lo, hi;
    asm("mov.b64 {%0, %1}, %2;" : "=f"(lo), "=f"(hi) : "l"(v));
    return make_float2(lo, hi);
}

// ---------------- init ----------------
__global__ void k_init(int N) {
    int i = blockIdx.x * blockDim.x + threadIdx.x;
    if (i < N) g_counts[i] = 0;
}

// ---------------- precompute fused weights ----------------
__global__ void k_pre(const float* __restrict__ Wk, const float* __restrict__ bk,
                      const float* __restrict__ Wv, const float* __restrict__ bv,
                      const float* __restrict__ Wq, const float* __restrict__ bq,
                      const float* __restrict__ Wo) {
    int i = blockIdx.x;     // 0..127
    int j = threadIdx.x;    // 0..127
    float a = 0.f, c = 0.f;
#pragma unroll 8
    for (int t = 0; t < D; t++) {
        a = fmaf(Wq[i * D + t], Wk[j * D + t], a);   // (Wq Wk^T)[i][j]
        c = fmaf(Wv[i * D + t], Wo[t * D + j], c);   // (Wv Wo)[i][j]
    }
    g_Wqk[i * D + j] = a;
    g_Wvo[i * D + j] = c;
    if (i == 0) {
        float b1 = 0.f, b2 = 0.f, b3 = 0.f;
#pragma unroll 8
        for (int t = 0; t < D; t++) {
            b1 = fmaf(bq[t], Wk[j * D + t], b1);     // (bq Wk^T)[j]
            b2 = fmaf(Wq[j * D + t], bk[t], b2);     // (Wq bk)[j]
            b3 = fmaf(bv[t], Wo[t * D + j], b3);     // (bv Wo)[j]
        }
        g_bqk[j] = b1; g_wqb[j] = b2; g_bvo[j] = b3;
        if (j == 0) {
            float b = 0.f;
            for (int t = 0; t < D; t++) b = fmaf(bq[t], bk[t], b);
            g_bqb[0] = b;
        }
    }
}

// ---------------- CSR build ----------------
__global__ void k_hist(const int* __restrict__ recv, int E) {
    for (int e = blockIdx.x * blockDim.x + threadIdx.x; e < E; e += gridDim.x * blockDim.x)
        atomicAdd(&g_counts[recv[e]], 1);
}

// multi-block scan: (1) per-block sums, (2) scan of block sums, (3) per-block scatter
__global__ void k_scan1(int N) {
    int i = blockIdx.x * 256 + threadIdx.x;
    int v = (i < N) ? g_counts[i] : 0;
    int lane = threadIdx.x & 31, wid = threadIdx.x >> 5;
#pragma unroll
    for (int off = 16; off > 0; off >>= 1) v += __shfl_xor_sync(0xffffffffu, v, off);
    __shared__ int ws[8];
    if (lane == 0) ws[wid] = v;
    __syncthreads();
    if (threadIdx.x == 0) {
        int s = 0;
#pragma unroll
        for (int w = 0; w < 8; w++) s += ws[w];
        g_bsum[blockIdx.x] = s;
    }
}

__global__ void k_scan2(int nb) {
    int tid = threadIdx.x;
    int v = (tid < nb) ? g_bsum[tid] : 0;
    int lane = tid & 31, wid = tid >> 5;
    int x = v;
#pragma unroll
    for (int off = 1; off < 32; off <<= 1) {
        int t = __shfl_up_sync(0xffffffffu, x, off);
        if (lane >= off) x += t;
    }
    __shared__ int ws[8];
    if (lane == 31) ws[wid] = x;
    __syncthreads();
    if (wid == 0) {
        int t = (lane < 8) ? ws[lane] : 0;
#pragma unroll
        for (int off = 1; off < 8; off <<= 1) {
            int u = __shfl_up_sync(0xffffffffu, t, off);
            if (lane >= off) t += u;
        }
        if (lane < 8) ws[lane] = t;
    }
    __syncthreads();
    int incl = x + (wid ? ws[wid - 1] : 0);
    if (tid < nb) g_bsum[tid] = incl - v;   // exclusive
}

__global__ void k_scan3(int N, int E) {
    int i = blockIdx.x * 256 + threadIdx.x;
    int v = (i < N) ? g_counts[i] : 0;
    int lane = threadIdx.x & 31, wid = threadIdx.x >> 5;
    int x = v;
#pragma unroll
    for (int off = 1; off < 32; off <<= 1) {
        int t = __shfl_up_sync(0xffffffffu, x, off);
        if (lane >= off) x += t;
    }
    __shared__ int ws[8];
    if (lane == 31) ws[wid] = x;
    __syncthreads();
    if (wid == 0) {
        int t = (lane < 8) ? ws[lane] : 0;
#pragma unroll
        for (int off = 1; off < 8; off <<= 1) {
            int u = __shfl_up_sync(0xffffffffu, t, off);
            if (lane >= off) t += u;
        }
        if (lane < 8) ws[lane] = t;
    }
    __syncthreads();
    int excl = x - v + (wid ? ws[wid - 1] : 0) + g_bsum[blockIdx.x];
    if (i < N) { g_offsets[i] = excl; g_cursor[i] = excl; }
    if (i == 0) g_offsets[N] = E;
}

__global__ void k_scatter(const int* __restrict__ recv, int E) {
    for (int e = blockIdx.x * blockDim.x + threadIdx.x; e < E; e += gridDim.x * blockDim.x) {
        int pos = atomicAdd(&g_cursor[recv[e]], 1);
        g_eids[pos] = e;
    }
}

// ---------------- pass 1: summed[n] = sum of messages over node's edges ----------------
__global__ void k_sum_nodes(const float* __restrict__ messages, int N) {
    int gw = (blockIdx.x * blockDim.x + threadIdx.x) >> 5;
    int lane = threadIdx.x & 31;
    if (gw >= N) return;
    int beg = g_offsets[gw], deg = g_offsets[gw + 1] - beg;
    const float4* m4 = (const float4*)messages;
    float4 acc = make_float4(0.f, 0.f, 0.f, 0.f);
    for (int k0 = 0; k0 < deg; k0 += 8) {
        int kb = deg - k0; if (kb > 8) kb = 8;
        int ee[8]; float4 mm[8];
#pragma unroll
        for (int j = 0; j < 8; j++) if (j < kb) ee[j] = __ldg(&g_eids[beg + k0 + j]);
#pragma unroll
        for (int j = 0; j < 8; j++) if (j < kb) mm[j] = __ldg(m4 + (size_t)ee[j] * 32 + lane);
#pragma unroll
        for (int j = 0; j < 8; j++) if (j < kb) {
            acc.x += mm[j].x; acc.y += mm[j].y; acc.z += mm[j].z; acc.w += mm[j].w;
        }
    }
    ((float4*)g_summed)[(size_t)gw * 32 + lane] = acc;
}

// ---------------- node projection (f32x2): qk = summed @ Wqk + bqk ; qb ----------------
__global__ void k_qkproj(int N) {
    const int TN = 16, P = 8;
    __shared__ __align__(16) float2 sp[P][D];
    int n0 = blockIdx.x * TN;
    int j = threadIdx.x;   // 0..127
#pragma unroll
    for (int p = 0; p < P; p++) {
        int na = n0 + 2 * p, nb = n0 + 2 * p + 1;
        if (na >= N) na = N - 1;
        if (nb >= N) nb = N - 1;
        sp[p][j] = make_float2(g_summed[(size_t)na * D + j], g_summed[(size_t)nb * D + j]);
    }
    __syncthreads();
    float bj = g_bqk[j];
    unsigned long long acc[P];
#pragma unroll
    for (int p = 0; p < P; p++) acc[p] = pk2(bj, bj);
#pragma unroll 4
    for (int i = 0; i < D; i++) {
        float w = __ldg(&g_Wqk[i * D + j]);
        unsigned long long bb = pk2(w, w);
#pragma unroll
        for (int p = 0; p < P; p++) {
            unsigned long long aa = *(const unsigned long long*)&sp[p][i];
            acc[p] = ffma2(aa, bb, acc[p]);
        }
    }
#pragma unroll
    for (int p = 0; p < P; p++) {
        float2 r = upk2(acc[p]);
        int na = n0 + 2 * p, nb = n0 + 2 * p + 1;
        if (na < N) g_qk[(size_t)na * D + j] = r.x;
        if (nb < N) g_qk[(size_t)nb * D + j] = r.y;
    }
    if (j < TN) {
        int n = n0 + j;
        if (n < N) {
            float a = g_bqb[0];
            for (int i = 0; i < D; i++) {
                float2 v = sp[j >> 1][i];
                a = fmaf((j & 1) ? v.y : v.x, g_wqb[i], a);
            }
            g_qb[n] = a;
        }
    }
}

// ---------------- pass 2: scores + warp-local softmax -> normalized weights ----------
__global__ void k_score(const float* __restrict__ messages, int N) {
    int gw = (blockIdx.x * blockDim.x + threadIdx.x) >> 5;
    int lane = threadIdx.x & 31;
    if (gw >= N) return;
    int beg = g_offsets[gw], deg = g_offsets[gw + 1] - beg;
    if (deg == 0) { if (lane == 0) g_sums[gw] = 0.f; return; }
    const float4* m4 = (const float4*)messages;
    float4 q = __ldg((const float4*)g_qk + (size_t)gw * 32 + lane);
    float qb = __ldg(&g_qb[gw]);
    float myscore = -CUDART_INF_F;
    int kmain = deg < 32 ? deg : 32;
    for (int k0 = 0; k0 < kmain; k0 += 8) {
        int kb = kmain - k0; if (kb > 8) kb = 8;
        int ee[8]; float4 mm[8];
#pragma unroll
        for (int j = 0; j < 8; j++) if (j < kb) ee[j] = __ldg(&g_eids[beg + k0 + j]);
#pragma unroll
        for (int j = 0; j < 8; j++) if (j < kb) mm[j] = __ldg(m4 + (size_t)ee[j] * 32 + lane);
#pragma unroll
        for (int j = 0; j < 8; j++) if (j < kb) {
            float d = mm[j].x * q.x + mm[j].y * q.y + mm[j].z * q.z + mm[j].w * q.w;
#pragma unroll
            for (int off = 16; off > 0; off >>= 1)
                d += __shfl_xor_sync(0xffffffffu, d, off);
            float s = (d + qb) * SCALE_INV;
            if (lane == k0 + j) myscore = s;
        }
    }
    // rare tail: deg > 32
    float tailmax = -CUDART_INF_F;
    for (int k = 32; k < deg; k++) {
        int e = __ldg(&g_eids[beg + k]);
        float4 m = __ldg(m4 + (size_t)e * 32 + lane);
        float d = m.x * q.x + m.y * q.y + m.z * q.z + m.w * q.w;
#pragma unroll
        for (int off = 16; off > 0; off >>= 1)
            d += __shfl_xor_sync(0xffffffffu, d, off);
        float s = (d + qb) * SCALE_INV;
        if (lane == 0) g_scores[beg + k] = s;
        tailmax = fmaxf(tailmax, s);
    }
    // warp max
    float mx = myscore;
#pragma unroll
    for (int off = 16; off > 0; off >>= 1)
        mx = fmaxf(mx, __shfl_xor_sync(0xffffffffu, mx, off));
    mx = fmaxf(mx, tailmax);
    // warp sum of exps
    float ex = (lane < kmain) ? __expf(myscore - mx) : 0.f;
    float p = ex;
#pragma unroll
    for (int off = 16; off > 0; off >>= 1)
        p += __shfl_xor_sync(0xffffffffu, p, off);
    float ptail = 0.f;
    for (int k = 32 + lane; k < deg; k += 32) ptail += __expf(g_scores[beg + k] - mx);
#pragma unroll
    for (int off = 16; off > 0; off >>= 1)
        ptail += __shfl_xor_sync(0xffffffffu, ptail, off);
    p += ptail;
    float inv = 1.f / (p + 1e-8f);
    if (lane == 0) g_sums[gw] = p;
    if (lane < kmain) g_att[beg + lane] = ex * inv;
    for (int k = 32 + lane; k < deg; k += 32)
        g_att[beg + k] = __expf(g_scores[beg + k] - mx) * inv;
}

// ---------------- pass 3: weighted aggregation ----------------
__global__ void k_agg(const float* __restrict__ messages, int N) {
    int gw = (blockIdx.x * blockDim.x + threadIdx.x) >> 5;
    int lane = threadIdx.x & 31;
    if (gw >= N) return;
    int beg = g_offsets[gw], deg = g_offsets[gw + 1] - beg;
    const float4* m4 = (const float4*)messages;
    float4 acc = make_float4(0.f, 0.f, 0.f, 0.f);
    for (int k0 = 0; k0 < deg; k0 += 8) {
        int kb = deg - k0; if (kb > 8) kb = 8;
        int ee[8]; float ww[8]; float4 mm[8];
#pragma unroll
        for (int j = 0; j < 8; j++) if (j < kb) {
            ee[j] = __ldg(&g_eids[beg + k0 + j]);
            ww[j] = __ldg(&g_att[beg + k0 + j]);
        }
#pragma unroll
        for (int j = 0; j < 8; j++) if (j < kb) mm[j] = __ldg(m4 + (size_t)ee[j] * 32 + lane);
#pragma unroll
        for (int j = 0; j < 8; j++) if (j < kb) {
            acc.x = fmaf(ww[j], mm[j].x, acc.x);
            acc.y = fmaf(ww[j], mm[j].y, acc.y);
            acc.z = fmaf(ww[j], mm[j].z, acc.z);
            acc.w = fmaf(ww[j], mm[j].w, acc.w);
        }
    }
    ((float4*)g_wm)[(size_t)gw * 32 + lane] = acc;
}

// ---------------- output projection (f32x2): out = wm @ Wvo + asum*bvo + bo ----------
__global__ void k_out(const float* __restrict__ bo, float* __restrict__ out, int N) {
    const int TN = 16, P = 8;
    __shared__ __align__(16) float2 sp[P][D];
    __shared__ float sas[TN];
    int n0 = blockIdx.x * TN;
    int j = threadIdx.x;
#pragma unroll
    for (int p = 0; p < P; p++) {
        int na = n0 + 2 * p, nb = n0 + 2 * p + 1;
        if (na >= N) na = N - 1;
        if (nb >= N) nb = N - 1;
        sp[p][j] = make_float2(g_wm[(size_t)na * D + j], g_wm[(size_t)nb * D + j]);
    }
    if (j < TN) {
        int n = n0 + j; if (n >= N) n = N - 1;
        float s = g_sums[n];
        sas[j] = s / (s + 1e-8f);
    }
    __syncthreads();
    float bvoj = g_bvo[j];
    float boj  = __ldg(bo + j);
    unsigned long long acc[P];
#pragma unroll
    for (int p = 0; p < P; p++)
        acc[p] = pk2(fmaf(sas[2 * p], bvoj, boj), fmaf(sas[2 * p + 1], bvoj, boj));
#pragma unroll 4
    for (int i = 0; i < D; i++) {
        float w = __ldg(&g_Wvo[i * D + j]);
        unsigned long long bb = pk2(w, w);
#pragma unroll
        for (int p = 0; p < P; p++) {
            unsigned long long aa = *(const unsigned long long*)&sp[p][i];
            acc[p] = ffma2(aa, bb, acc[p]);
        }
    }
#pragma unroll
    for (int p = 0; p < P; p++) {
        float2 r = upk2(acc[p]);
        int na = n0 + 2 * p, nb = n0 + 2 * p + 1;
        if (na < N) out[(size_t)na * D + j] = r.x;
        if (nb < N) out[(size_t)nb * D + j] = r.y;
    }
}

// ---------------- launch ----------------
extern "C" void kernel_launch(void* const* d_in, const int* in_sizes, int n_in,
                              void* d_out, int out_size) {
    const float* messages = (const float*)d_in[0];
    const int*   recv     = (const int*)d_in[1];
    int wb = (n_in >= 11) ? 3 : 2;
    const float* Wk = (const float*)d_in[wb + 0];
    const float* bk = (const float*)d_in[wb + 1];
    const float* Wv = (const float*)d_in[wb + 2];
    const float* bv = (const float*)d_in[wb + 3];
    const float* Wq = (const float*)d_in[wb + 4];
    const float* bq = (const float*)d_in[wb + 5];
    const float* Wo = (const float*)d_in[wb + 6];
    const float* bo = (const float*)d_in[wb + 7];
    float* out = (float*)d_out;

    int E = in_sizes[0] / D;
    int N = out_size / D;
    int nb = (N + 255) / 256;

    k_init<<<(N + 255) / 256, 256>>>(N);
    k_pre<<<D, D>>>(Wk, bk, Wv, bv, Wq, bq, Wo);
    k_hist<<<(E + 255) / 256, 256>>>(recv, E);
    k_scan1<<<nb, 256>>>(N);
    k_scan2<<<1, 256>>>(nb);
    k_scan3<<<nb, 256>>>(N, E);
    k_scatter<<<(E + 255) / 256, 256>>>(recv, E);
    k_sum_nodes<<<(N + 7) / 8, 256>>>(messages, N);
    k_qkproj<<<(N + 15) / 16, 128>>>(N);
    k_score<<<(N + 7) / 8, 256>>>(messages, N);
    k_agg<<<(N + 7) / 8, 256>>>(messages, N);
    k_out<<<(N + 15) / 16, 128>>>(bo, out, N);
}